// round 2
// baseline (speedup 1.0000x reference)
#include <cuda_runtime.h>
#include <cuda_bf16.h>

#define N_NODES 40000
#define N_EDGES 640000
#define HIDDEN  128
#define N_GRAPHS 256
#define N_CLASSES 5

// ---------------- scratch (static device globals; no runtime alloc) ----------
__device__ float g_y[N_NODES * HIDDEN];     // dinv-scaled GEMM output (gather source)
__device__ float g_h[N_NODES * HIDDEN];     // aggregated / activated features
__device__ float g_dinv[N_NODES];
__device__ int   g_deg[N_NODES];
__device__ int   g_rowptr[N_NODES + 1];
__device__ int   g_cursor[N_NODES];
__device__ int   g_csrc[N_EDGES];
__device__ float g_s[N_GRAPHS * HIDDEN];    // pooled means
__device__ float g_WC[HIDDEN * N_CLASSES];  // W3 @ Wl
__device__ float g_bc[N_CLASSES];           // b3 @ Wl + bl

// ---------------- CSR build ---------------------------------------------------
__global__ void init_deg_kernel() {
    int i = blockIdx.x * blockDim.x + threadIdx.x;
    if (i < N_NODES) g_deg[i] = 0;
}

__global__ void count_deg_kernel(const int* __restrict__ ei) {
    int e = blockIdx.x * blockDim.x + threadIdx.x;
    if (e < N_EDGES) atomicAdd(&g_deg[ei[N_EDGES + e]], 1);  // dst row
}

// single-block exclusive scan over 40000 ints; also writes cursor + dinv
__global__ void scan_kernel() {
    const int NT = 1024;
    int tid = threadIdx.x;
    int lane = tid & 31, wid = tid >> 5;
    __shared__ int wsum[32];
    __shared__ int s_carry;
    if (tid == 0) s_carry = 0;
    __syncthreads();
    for (int base = 0; base < N_NODES; base += NT) {
        int i = base + tid;
        int v = (i < N_NODES) ? g_deg[i] : 0;
        int x = v;
        #pragma unroll
        for (int d = 1; d < 32; d <<= 1) {
            int t = __shfl_up_sync(0xffffffffu, x, d);
            if (lane >= d) x += t;
        }
        if (lane == 31) wsum[wid] = x;
        __syncthreads();
        if (wid == 0) {
            int w = wsum[lane];
            #pragma unroll
            for (int d = 1; d < 32; d <<= 1) {
                int t = __shfl_up_sync(0xffffffffu, w, d);
                if (lane >= d) w += t;
            }
            wsum[lane] = w;
        }
        __syncthreads();
        int carry = s_carry;
        int woff = (wid == 0) ? 0 : wsum[wid - 1];
        int incl = x + woff + carry;
        int excl = incl - v;
        if (i < N_NODES) {
            g_rowptr[i] = excl;
            g_cursor[i] = excl;
            g_dinv[i]   = rsqrtf((float)(v + 1));  // +1 self loop
        }
        __syncthreads();
        if (tid == NT - 1) s_carry = incl;
        __syncthreads();
    }
    if (tid == 0) g_rowptr[N_NODES] = s_carry;
}

__global__ void fill_csr_kernel(const int* __restrict__ ei) {
    int e = blockIdx.x * blockDim.x + threadIdx.x;
    if (e < N_EDGES) {
        int dst = ei[N_EDGES + e];
        int src = ei[e];
        int p = atomicAdd(&g_cursor[dst], 1);
        g_csrc[p] = src;
    }
}

// ---------------- GEMM: Y[i,:] = dinv[i] * (A[i,:] @ W) -----------------------
// A: [N_NODES,128], W: [128,128]. 256 threads, BM=128, 8x8 microtile, BK=32.
__global__ __launch_bounds__(256) void gemm_dinv_kernel(
    const float* __restrict__ A, const float* __restrict__ W, float* __restrict__ Y)
{
    __shared__ __align__(16) float As[32 * 132];  // [k][row], padded row-dim stride 132
    __shared__ __align__(16) float Bs[32 * 128];  // [k][col]

    int tid = threadIdx.x;
    int tx = tid & 15;        // col group
    int ty = tid >> 4;        // row group
    int row0 = blockIdx.x * 128;

    float acc[8][8];
    #pragma unroll
    for (int i = 0; i < 8; i++)
        #pragma unroll
        for (int j = 0; j < 8; j++) acc[i][j] = 0.f;

    for (int k0 = 0; k0 < 128; k0 += 32) {
        // load A chunk (128 rows x 32 k) transposed into As[k][row]
        #pragma unroll
        for (int j = 0; j < 4; j++) {
            int f = tid + 256 * j;          // 0..1023
            int r = f >> 3;                 // 0..127
            int kk = (f & 7) * 4;           // 0..28
            float4 v = make_float4(0.f, 0.f, 0.f, 0.f);
            int gr = row0 + r;
            if (gr < N_NODES)
                v = *reinterpret_cast<const float4*>(&A[gr * 128 + k0 + kk]);
            As[(kk + 0) * 132 + r] = v.x;
            As[(kk + 1) * 132 + r] = v.y;
            As[(kk + 2) * 132 + r] = v.z;
            As[(kk + 3) * 132 + r] = v.w;
        }
        // load B chunk (32 k x 128 cols)
        #pragma unroll
        for (int j = 0; j < 4; j++) {
            int f = tid + 256 * j;          // 0..1023
            int r = f >> 5;                 // 0..31
            int c = (f & 31) * 4;           // 0..124
            float4 v = *reinterpret_cast<const float4*>(&W[(k0 + r) * 128 + c]);
            *reinterpret_cast<float4*>(&Bs[r * 128 + c]) = v;
        }
        __syncthreads();

        #pragma unroll
        for (int k = 0; k < 32; k++) {
            float4 a0 = *reinterpret_cast<const float4*>(&As[k * 132 + ty * 8]);
            float4 a1 = *reinterpret_cast<const float4*>(&As[k * 132 + ty * 8 + 4]);
            float4 b0 = *reinterpret_cast<const float4*>(&Bs[k * 128 + tx * 8]);
            float4 b1 = *reinterpret_cast<const float4*>(&Bs[k * 128 + tx * 8 + 4]);
            float a[8] = {a0.x, a0.y, a0.z, a0.w, a1.x, a1.y, a1.z, a1.w};
            float b[8] = {b0.x, b0.y, b0.z, b0.w, b1.x, b1.y, b1.z, b1.w};
            #pragma unroll
            for (int i = 0; i < 8; i++)
                #pragma unroll
                for (int j = 0; j < 8; j++) acc[i][j] = fmaf(a[i], b[j], acc[i][j]);
        }
        __syncthreads();
    }

    #pragma unroll
    for (int i = 0; i < 8; i++) {
        int r = row0 + ty * 8 + i;
        if (r < N_NODES) {
            float d = g_dinv[r];
            float4 o0 = make_float4(d * acc[i][0], d * acc[i][1], d * acc[i][2], d * acc[i][3]);
            float4 o1 = make_float4(d * acc[i][4], d * acc[i][5], d * acc[i][6], d * acc[i][7]);
            *reinterpret_cast<float4*>(&Y[r * 128 + tx * 8])     = o0;
            *reinterpret_cast<float4*>(&Y[r * 128 + tx * 8 + 4]) = o1;
        }
    }
}

// ---------------- Aggregation: out[i] = act(dinv[i]*(y[i]+sum y[src]) + b) ----
// one warp per node; each lane owns a float4 feature chunk.
__global__ __launch_bounds__(256) void agg_kernel(
    const float* __restrict__ y, float* __restrict__ out,
    const float* __restrict__ bias, int do_relu)
{
    int warp = (blockIdx.x * blockDim.x + threadIdx.x) >> 5;
    int lane = threadIdx.x & 31;
    if (warp >= N_NODES) return;

    const float4* y4 = reinterpret_cast<const float4*>(y);
    float4 acc = y4[warp * 32 + lane];     // self-loop contribution
    int beg = g_rowptr[warp];
    int end = g_rowptr[warp + 1];

    int e = beg;
    // 2-deep pipelined edge loop
    int s_next = (e < end) ? __ldg(&g_csrc[e]) : 0;
    for (; e < end; e++) {
        int s = s_next;
        if (e + 1 < end) s_next = __ldg(&g_csrc[e + 1]);
        float4 v = y4[s * 32 + lane];
        acc.x += v.x; acc.y += v.y; acc.z += v.z; acc.w += v.w;
    }

    float d = g_dinv[warp];
    float4 b = bias ? reinterpret_cast<const float4*>(bias)[lane]
                    : make_float4(0.f, 0.f, 0.f, 0.f);
    float4 r;
    r.x = fmaf(d, acc.x, b.x);
    r.y = fmaf(d, acc.y, b.y);
    r.z = fmaf(d, acc.z, b.z);
    r.w = fmaf(d, acc.w, b.w);
    if (do_relu) {
        r.x = fmaxf(r.x, 0.f); r.y = fmaxf(r.y, 0.f);
        r.z = fmaxf(r.z, 0.f); r.w = fmaxf(r.w, 0.f);
    }
    reinterpret_cast<float4*>(out)[warp * 32 + lane] = r;
}

// ---------------- y = dinv * h (elementwise, for reassociated layer 3) --------
__global__ void scale_kernel(const float* __restrict__ h, float* __restrict__ y) {
    int i = blockIdx.x * blockDim.x + threadIdx.x;  // float4 index
    if (i < N_NODES * 32) {
        float d = g_dinv[i >> 5];
        float4 v = reinterpret_cast<const float4*>(h)[i];
        v.x *= d; v.y *= d; v.z *= d; v.w *= d;
        reinterpret_cast<float4*>(y)[i] = v;
    }
}

// ---------------- mean pool over sorted batch ---------------------------------
__global__ __launch_bounds__(128) void pool_kernel(const int* __restrict__ batch,
                                                   const float* __restrict__ h)
{
    int g = blockIdx.x;          // graph id
    __shared__ int s_beg, s_end;
    if (threadIdx.x == 0) {
        int lo = 0, hi = N_NODES;
        while (lo < hi) { int m = (lo + hi) >> 1; if (batch[m] < g) lo = m + 1; else hi = m; }
        s_beg = lo;
        lo = 0; hi = N_NODES;
        while (lo < hi) { int m = (lo + hi) >> 1; if (batch[m] < g + 1) lo = m + 1; else hi = m; }
        s_end = lo;
    }
    __syncthreads();
    int f = threadIdx.x;
    float sum = 0.f;
    for (int n = s_beg; n < s_end; n++) sum += h[n * 128 + f];
    float cnt = (float)(s_end - s_beg);
    g_s[g * 128 + f] = sum / fmaxf(cnt, 1.0f);
}

// ---------------- head fold: WC = W3@Wl, bc = b3@Wl + bl ----------------------
__global__ void head_fold_kernel(const float* __restrict__ W3, const float* __restrict__ b3,
                                 const float* __restrict__ Wl, const float* __restrict__ bl)
{
    int t = threadIdx.x;
    if (t < HIDDEN * N_CLASSES) {
        int j = t / N_CLASSES, c = t % N_CLASSES;
        float s = 0.f;
        for (int k = 0; k < HIDDEN; k++) s = fmaf(W3[j * HIDDEN + k], Wl[k * N_CLASSES + c], s);
        g_WC[t] = s;
    } else if (t < HIDDEN * N_CLASSES + N_CLASSES) {
        int c = t - HIDDEN * N_CLASSES;
        float s = bl[c];
        for (int k = 0; k < HIDDEN; k++) s = fmaf(b3[k], Wl[k * N_CLASSES + c], s);
        g_bc[c] = s;
    }
}

// ---------------- out[g,c] = s[g,:] @ WC[:,c] + bc[c] -------------------------
__global__ void out_kernel(float* __restrict__ out) {
    int t = blockIdx.x * blockDim.x + threadIdx.x;
    if (t < N_GRAPHS * N_CLASSES) {
        int g = t / N_CLASSES, c = t % N_CLASSES;
        float s = g_bc[c];
        for (int k = 0; k < HIDDEN; k++) s = fmaf(g_s[g * 128 + k], g_WC[k * N_CLASSES + c], s);
        out[t] = s;
    }
}

// ---------------- launcher ----------------------------------------------------
extern "C" void kernel_launch(void* const* d_in, const int* in_sizes, int n_in,
                              void* d_out, int out_size)
{
    const float* x     = (const float*)d_in[0];
    const int*   ei    = (const int*)  d_in[1];
    const int*   batch = (const int*)  d_in[2];
    const float* W1    = (const float*)d_in[3];
    const float* b1    = (const float*)d_in[4];
    const float* W2    = (const float*)d_in[5];
    const float* b2    = (const float*)d_in[6];
    const float* W3    = (const float*)d_in[7];
    const float* b3    = (const float*)d_in[8];
    const float* Wl    = (const float*)d_in[9];
    const float* bl    = (const float*)d_in[10];
    float* out = (float*)d_out;

    float *yb, *hb;
    cudaGetSymbolAddress((void**)&yb, g_y);
    cudaGetSymbolAddress((void**)&hb, g_h);

    const int EB = (N_EDGES + 255) / 256;
    const int GEMM_BLOCKS = (N_NODES + 127) / 128;
    const int AGG_BLOCKS  = (N_NODES + 7) / 8;      // 8 warps per 256-thread block
    const int SC_BLOCKS   = (N_NODES * 32 + 255) / 256;

    // CSR build (per call; deterministic up to within-bucket order)
    init_deg_kernel<<<(N_NODES + 255) / 256, 256>>>();
    count_deg_kernel<<<EB, 256>>>(ei);
    scan_kernel<<<1, 1024>>>();
    fill_csr_kernel<<<EB, 256>>>(ei);

    // layer 1
    gemm_dinv_kernel<<<GEMM_BLOCKS, 256>>>(x, W1, yb);
    agg_kernel<<<AGG_BLOCKS, 256>>>(yb, hb, b1, 1);
    // layer 2
    gemm_dinv_kernel<<<GEMM_BLOCKS, 256>>>(hb, W2, yb);
    agg_kernel<<<AGG_BLOCKS, 256>>>(yb, hb, b2, 1);
    // layer 3 (reassociated: aggregate first, GEMM after pooling)
    scale_kernel<<<SC_BLOCKS, 256>>>(hb, yb);
    agg_kernel<<<AGG_BLOCKS, 256>>>(yb, hb, (const float*)nullptr, 0);

    // pool + folded head
    pool_kernel<<<N_GRAPHS, 128>>>(batch, hb);
    head_fold_kernel<<<1, HIDDEN * N_CLASSES + N_CLASSES>>>(W3, b3, Wl, bl);
    out_kernel<<<(N_GRAPHS * N_CLASSES + 255) / 256, 256>>>(out);
}

// round 3
// speedup vs baseline: 1.0914x; 1.0914x over previous
#include <cuda_runtime.h>
#include <cuda_bf16.h>

#define N_NODES 40000
#define N_EDGES 640000
#define HIDDEN  128
#define N_GRAPHS 256
#define N_CLASSES 5

// ---------------- scratch (static device globals; no runtime alloc) ----------
__device__ float g_y[N_NODES * HIDDEN];     // dinv-scaled GEMM output (gather source)
__device__ float g_h[N_NODES * HIDDEN];     // aggregated / activated features
__device__ float g_dinv[N_NODES];
__device__ int   g_deg[N_NODES];
__device__ int   g_rowptr[N_NODES + 1];
__device__ int   g_cursor[N_NODES];
__device__ int   g_csrc[N_EDGES];
__device__ float g_s[N_GRAPHS * HIDDEN];    // pooled means
__device__ float g_WC[HIDDEN * N_CLASSES];  // W3 @ Wl
__device__ float g_bc[N_CLASSES];           // b3 @ Wl + bl

// ---------------- CSR build ---------------------------------------------------
__global__ void init_deg_kernel() {
    int i = blockIdx.x * blockDim.x + threadIdx.x;
    if (i < N_NODES) g_deg[i] = 0;
}

__global__ void count_deg_kernel(const int* __restrict__ ei) {
    int e = blockIdx.x * blockDim.x + threadIdx.x;
    if (e < N_EDGES) atomicAdd(&g_deg[ei[N_EDGES + e]], 1);  // dst row
}

// single-block exclusive scan over 40000 ints; also writes cursor + dinv
__global__ void scan_kernel() {
    const int NT = 1024;
    int tid = threadIdx.x;
    int lane = tid & 31, wid = tid >> 5;
    __shared__ int wsum[32];
    __shared__ int s_carry;
    if (tid == 0) s_carry = 0;
    __syncthreads();
    for (int base = 0; base < N_NODES; base += NT) {
        int i = base + tid;
        int v = (i < N_NODES) ? g_deg[i] : 0;
        int x = v;
        #pragma unroll
        for (int d = 1; d < 32; d <<= 1) {
            int t = __shfl_up_sync(0xffffffffu, x, d);
            if (lane >= d) x += t;
        }
        if (lane == 31) wsum[wid] = x;
        __syncthreads();
        if (wid == 0) {
            int w = wsum[lane];
            #pragma unroll
            for (int d = 1; d < 32; d <<= 1) {
                int t = __shfl_up_sync(0xffffffffu, w, d);
                if (lane >= d) w += t;
            }
            wsum[lane] = w;
        }
        __syncthreads();
        int carry = s_carry;
        int woff = (wid == 0) ? 0 : wsum[wid - 1];
        int incl = x + woff + carry;
        int excl = incl - v;
        if (i < N_NODES) {
            g_rowptr[i] = excl;
            g_cursor[i] = excl;
            g_dinv[i]   = rsqrtf((float)(v + 1));  // +1 self loop
        }
        __syncthreads();
        if (tid == NT - 1) s_carry = incl;
        __syncthreads();
    }
    if (tid == 0) g_rowptr[N_NODES] = s_carry;
}

__global__ void fill_csr_kernel(const int* __restrict__ ei) {
    int e = blockIdx.x * blockDim.x + threadIdx.x;
    if (e < N_EDGES) {
        int dst = ei[N_EDGES + e];
        int src = ei[e];
        int p = atomicAdd(&g_cursor[dst], 1);
        g_csrc[p] = src;
    }
}

// ---------------- GEMM: Y[i,:] = dinv[i] * (A[i,:] @ W) -----------------------
// A: [N_NODES,128], W: [128,128]. 256 threads, BM=128, 8x8 microtile, BK=32.
__global__ __launch_bounds__(256) void gemm_dinv_kernel(
    const float* __restrict__ A, const float* __restrict__ W, float* __restrict__ Y)
{
    __shared__ __align__(16) float As[32 * 132];  // [k][row], padded row-dim stride 132
    __shared__ __align__(16) float Bs[32 * 128];  // [k][col]

    int tid = threadIdx.x;
    int tx = tid & 15;        // col group
    int ty = tid >> 4;        // row group
    int row0 = blockIdx.x * 128;

    float acc[8][8];
    #pragma unroll
    for (int i = 0; i < 8; i++)
        #pragma unroll
        for (int j = 0; j < 8; j++) acc[i][j] = 0.f;

    for (int k0 = 0; k0 < 128; k0 += 32) {
        // load A chunk (128 rows x 32 k) transposed into As[k][row]
        #pragma unroll
        for (int j = 0; j < 4; j++) {
            int f = tid + 256 * j;          // 0..1023
            int r = f >> 3;                 // 0..127
            int kk = (f & 7) * 4;           // 0..28
            float4 v = make_float4(0.f, 0.f, 0.f, 0.f);
            int gr = row0 + r;
            if (gr < N_NODES)
                v = *reinterpret_cast<const float4*>(&A[gr * 128 + k0 + kk]);
            As[(kk + 0) * 132 + r] = v.x;
            As[(kk + 1) * 132 + r] = v.y;
            As[(kk + 2) * 132 + r] = v.z;
            As[(kk + 3) * 132 + r] = v.w;
        }
        // load B chunk (32 k x 128 cols)
        #pragma unroll
        for (int j = 0; j < 4; j++) {
            int f = tid + 256 * j;          // 0..1023
            int r = f >> 5;                 // 0..31
            int c = (f & 31) * 4;           // 0..124
            float4 v = *reinterpret_cast<const float4*>(&W[(k0 + r) * 128 + c]);
            *reinterpret_cast<float4*>(&Bs[r * 128 + c]) = v;
        }
        __syncthreads();

        #pragma unroll
        for (int k = 0; k < 32; k++) {
            float4 a0 = *reinterpret_cast<const float4*>(&As[k * 132 + ty * 8]);
            float4 a1 = *reinterpret_cast<const float4*>(&As[k * 132 + ty * 8 + 4]);
            float4 b0 = *reinterpret_cast<const float4*>(&Bs[k * 128 + tx * 8]);
            float4 b1 = *reinterpret_cast<const float4*>(&Bs[k * 128 + tx * 8 + 4]);
            float a[8] = {a0.x, a0.y, a0.z, a0.w, a1.x, a1.y, a1.z, a1.w};
            float b[8] = {b0.x, b0.y, b0.z, b0.w, b1.x, b1.y, b1.z, b1.w};
            #pragma unroll
            for (int i = 0; i < 8; i++)
                #pragma unroll
                for (int j = 0; j < 8; j++) acc[i][j] = fmaf(a[i], b[j], acc[i][j]);
        }
        __syncthreads();
    }

    #pragma unroll
    for (int i = 0; i < 8; i++) {
        int r = row0 + ty * 8 + i;
        if (r < N_NODES) {
            float d = g_dinv[r];
            float4 o0 = make_float4(d * acc[i][0], d * acc[i][1], d * acc[i][2], d * acc[i][3]);
            float4 o1 = make_float4(d * acc[i][4], d * acc[i][5], d * acc[i][6], d * acc[i][7]);
            *reinterpret_cast<float4*>(&Y[r * 128 + tx * 8])     = o0;
            *reinterpret_cast<float4*>(&Y[r * 128 + tx * 8 + 4]) = o1;
        }
    }
}

// ---------------- Aggregation: out[i] = act(dinv[i]*(y[i]+sum y[src]) + b) ----
// one warp per node; each lane owns a float4 feature chunk.
__global__ __launch_bounds__(256) void agg_kernel(
    const float* __restrict__ y, float* __restrict__ out,
    const float* __restrict__ bias, int do_relu)
{
    int warp = (blockIdx.x * blockDim.x + threadIdx.x) >> 5;
    int lane = threadIdx.x & 31;
    if (warp >= N_NODES) return;

    const float4* y4 = reinterpret_cast<const float4*>(y);
    float4 acc = y4[warp * 32 + lane];     // self-loop contribution
    int beg = g_rowptr[warp];
    int end = g_rowptr[warp + 1];

    int e = beg;
    // 2-deep pipelined edge loop
    int s_next = (e < end) ? __ldg(&g_csrc[e]) : 0;
    for (; e < end; e++) {
        int s = s_next;
        if (e + 1 < end) s_next = __ldg(&g_csrc[e + 1]);
        float4 v = y4[s * 32 + lane];
        acc.x += v.x; acc.y += v.y; acc.z += v.z; acc.w += v.w;
    }

    float d = g_dinv[warp];
    float4 b = bias ? reinterpret_cast<const float4*>(bias)[lane]
                    : make_float4(0.f, 0.f, 0.f, 0.f);
    float4 r;
    r.x = fmaf(d, acc.x, b.x);
    r.y = fmaf(d, acc.y, b.y);
    r.z = fmaf(d, acc.z, b.z);
    r.w = fmaf(d, acc.w, b.w);
    if (do_relu) {
        r.x = fmaxf(r.x, 0.f); r.y = fmaxf(r.y, 0.f);
        r.z = fmaxf(r.z, 0.f); r.w = fmaxf(r.w, 0.f);
    }
    reinterpret_cast<float4*>(out)[warp * 32 + lane] = r;
}

// ---------------- y = dinv * h (elementwise, for reassociated layer 3) --------
__global__ void scale_kernel(const float* __restrict__ h, float* __restrict__ y) {
    int i = blockIdx.x * blockDim.x + threadIdx.x;  // float4 index
    if (i < N_NODES * 32) {
        float d = g_dinv[i >> 5];
        float4 v = reinterpret_cast<const float4*>(h)[i];
        v.x *= d; v.y *= d; v.z *= d; v.w *= d;
        reinterpret_cast<float4*>(y)[i] = v;
    }
}

// ---------------- mean pool over sorted batch ---------------------------------
__global__ __launch_bounds__(128) void pool_kernel(const int* __restrict__ batch,
                                                   const float* __restrict__ h)
{
    int g = blockIdx.x;          // graph id
    __shared__ int s_beg, s_end;
    if (threadIdx.x == 0) {
        int lo = 0, hi = N_NODES;
        while (lo < hi) { int m = (lo + hi) >> 1; if (batch[m] < g) lo = m + 1; else hi = m; }
        s_beg = lo;
        lo = 0; hi = N_NODES;
        while (lo < hi) { int m = (lo + hi) >> 1; if (batch[m] < g + 1) lo = m + 1; else hi = m; }
        s_end = lo;
    }
    __syncthreads();
    int f = threadIdx.x;
    float sum = 0.f;
    for (int n = s_beg; n < s_end; n++) sum += h[n * 128 + f];
    float cnt = (float)(s_end - s_beg);
    g_s[g * 128 + f] = sum / fmaxf(cnt, 1.0f);
}

// ---------------- head fold: WC = W3@Wl, bc = b3@Wl + bl ----------------------
__global__ void head_fold_kernel(const float* __restrict__ W3, const float* __restrict__ b3,
                                 const float* __restrict__ Wl, const float* __restrict__ bl)
{
    int t = threadIdx.x;
    if (t < HIDDEN * N_CLASSES) {
        int j = t / N_CLASSES, c = t % N_CLASSES;
        float s = 0.f;
        for (int k = 0; k < HIDDEN; k++) s = fmaf(W3[j * HIDDEN + k], Wl[k * N_CLASSES + c], s);
        g_WC[t] = s;
    } else if (t < HIDDEN * N_CLASSES + N_CLASSES) {
        int c = t - HIDDEN * N_CLASSES;
        float s = bl[c];
        for (int k = 0; k < HIDDEN; k++) s = fmaf(b3[k], Wl[k * N_CLASSES + c], s);
        g_bc[c] = s;
    }
}

// ---------------- out[g,c] = s[g,:] @ WC[:,c] + bc[c] -------------------------
__global__ void out_kernel(float* __restrict__ out) {
    int t = blockIdx.x * blockDim.x + threadIdx.x;
    if (t < N_GRAPHS * N_CLASSES) {
        int g = t / N_CLASSES, c = t % N_CLASSES;
        float s = g_bc[c];
        for (int k = 0; k < HIDDEN; k++) s = fmaf(g_s[g * 128 + k], g_WC[k * N_CLASSES + c], s);
        out[t] = s;
    }
}

// ---------------- launcher ----------------------------------------------------
extern "C" void kernel_launch(void* const* d_in, const int* in_sizes, int n_in,
                              void* d_out, int out_size)
{
    const float* x     = (const float*)d_in[0];
    const int*   ei    = (const int*)  d_in[1];
    const int*   batch = (const int*)  d_in[2];
    const float* W1    = (const float*)d_in[3];
    const float* b1    = (const float*)d_in[4];
    const float* W2    = (const float*)d_in[5];
    const float* b2    = (const float*)d_in[6];
    const float* W3    = (const float*)d_in[7];
    const float* b3    = (const float*)d_in[8];
    const float* Wl    = (const float*)d_in[9];
    const float* bl    = (const float*)d_in[10];
    float* out = (float*)d_out;

    float *yb, *hb;
    cudaGetSymbolAddress((void**)&yb, g_y);
    cudaGetSymbolAddress((void**)&hb, g_h);

    const int EB = (N_EDGES + 255) / 256;
    const int GEMM_BLOCKS = (N_NODES + 127) / 128;
    const int AGG_BLOCKS  = (N_NODES + 7) / 8;      // 8 warps per 256-thread block
    const int SC_BLOCKS   = (N_NODES * 32 + 255) / 256;

    // CSR build (per call; deterministic up to within-bucket order)
    init_deg_kernel<<<(N_NODES + 255) / 256, 256>>>();
    count_deg_kernel<<<EB, 256>>>(ei);
    scan_kernel<<<1, 1024>>>();
    fill_csr_kernel<<<EB, 256>>>(ei);

    // layer 1
    gemm_dinv_kernel<<<GEMM_BLOCKS, 256>>>(x, W1, yb);
    agg_kernel<<<AGG_BLOCKS, 256>>>(yb, hb, b1, 1);
    // layer 2
    gemm_dinv_kernel<<<GEMM_BLOCKS, 256>>>(hb, W2, yb);
    agg_kernel<<<AGG_BLOCKS, 256>>>(yb, hb, b2, 1);
    // layer 3 (reassociated: aggregate first, GEMM after pooling)
    scale_kernel<<<SC_BLOCKS, 256>>>(hb, yb);
    agg_kernel<<<AGG_BLOCKS, 256>>>(yb, hb, (const float*)nullptr, 0);

    // pool + folded head
    pool_kernel<<<N_GRAPHS, 128>>>(batch, hb);
    head_fold_kernel<<<1, HIDDEN * N_CLASSES + N_CLASSES>>>(W3, b3, Wl, bl);
    out_kernel<<<(N_GRAPHS * N_CLASSES + 255) / 256, 256>>>(out);
}